// round 5
// baseline (speedup 1.0000x reference)
#include <cuda_runtime.h>

#define UNITS   64
#define TT      512
#define BB      32
#define MOTOR   4
#define UNFOLDS 6
#define MROWS   (BB*TT)      // 16384

// ---------------- scratch (device globals: no allocation allowed) -----------
__device__ float g_buf0[MROWS * 500];
__device__ float g_buf1[MROWS * 500];
__device__ float g_h20 [MROWS * 20];
__device__ float g_o4  [MROWS * 4];

__device__ __forceinline__ float fast_tanh(float x) {
    float r;
    asm("tanh.approx.f32 %0, %1;" : "=f"(r) : "f"(x));
    return r;
}
__device__ __forceinline__ float fast_rcp(float x) {
    float r;
    asm("rcp.approx.f32 %0, %1;" : "=f"(r) : "f"(x));
    return r;
}

// ---------------- fused GEMM: C = act(A[M,K] @ W[K,N] + b) -------------------
// BM=BN=128, BK=8, 256 threads, 8x8 per-thread tile, double-buffered SMEM
// with register prefetch (1 barrier per K-iteration).
template <int ACT>
__global__ __launch_bounds__(256, 2)
void gemm_bias_act(const float* __restrict__ A, const float* __restrict__ W,
                   const float* __restrict__ bias, float* __restrict__ C,
                   int N, int K)
{
    __shared__ float As[2][8][128];
    __shared__ float Bs[2][8][132];

    const int tid = threadIdx.x;
    const int block_row = blockIdx.y * 128;
    const int block_col = blockIdx.x * 128;

    const int tx = tid & 15;
    const int ty = tid >> 4;

    const int a_r = tid >> 1;
    const int a_c = (tid & 1) * 4;
    const int b_r = tid >> 5;
    const int b_c = (tid & 31) * 4;

    const float* Arow = A + (size_t)(block_row + a_r) * K;

    float acc[8][8];
#pragma unroll
    for (int i = 0; i < 8; i++)
#pragma unroll
        for (int j = 0; j < 8; j++) acc[i][j] = 0.f;

    const int niter = (K + 7) / 8;
    float ra[4], rb[4];

    {
#pragma unroll
        for (int u = 0; u < 4; u++) {
            int k = a_c + u;
            ra[u] = (k < K) ? Arow[k] : 0.f;
        }
        int kb = b_r;
#pragma unroll
        for (int u = 0; u < 4; u++) {
            int col = block_col + b_c + u;
            rb[u] = (kb < K && col < N) ? W[(size_t)kb * N + col] : 0.f;
        }
#pragma unroll
        for (int u = 0; u < 4; u++) As[0][a_c + u][a_r] = ra[u];
#pragma unroll
        for (int u = 0; u < 4; u++) Bs[0][b_r][b_c + u] = rb[u];
    }
    __syncthreads();

    for (int it = 0; it < niter; it++) {
        const int p = it & 1;

        if (it + 1 < niter) {
            int k0 = (it + 1) * 8;
#pragma unroll
            for (int u = 0; u < 4; u++) {
                int k = k0 + a_c + u;
                ra[u] = (k < K) ? Arow[k] : 0.f;
            }
            int kb = k0 + b_r;
#pragma unroll
            for (int u = 0; u < 4; u++) {
                int col = block_col + b_c + u;
                rb[u] = (kb < K && col < N) ? W[(size_t)kb * N + col] : 0.f;
            }
        }

#pragma unroll
        for (int kk = 0; kk < 8; kk++) {
            float ar[8], br[8];
#pragma unroll
            for (int i = 0; i < 8; i++) ar[i] = As[p][kk][ty * 8 + i];
#pragma unroll
            for (int j = 0; j < 8; j++) br[j] = Bs[p][kk][tx * 8 + j];
#pragma unroll
            for (int i = 0; i < 8; i++)
#pragma unroll
                for (int j = 0; j < 8; j++)
                    acc[i][j] += ar[i] * br[j];
        }

        if (it + 1 < niter) {
#pragma unroll
            for (int u = 0; u < 4; u++) As[p ^ 1][a_c + u][a_r] = ra[u];
#pragma unroll
            for (int u = 0; u < 4; u++) Bs[p ^ 1][b_r][b_c + u] = rb[u];
        }
        __syncthreads();
    }

#pragma unroll
    for (int i = 0; i < 8; i++) {
        int row = block_row + ty * 8 + i;
#pragma unroll
        for (int j = 0; j < 8; j++) {
            int col = block_col + tx * 8 + j;
            if (col < N) {
                float v = acc[i][j] + bias[col];
                if (ACT) v = fast_tanh(v);
                C[(size_t)row * N + col] = v;
            }
        }
    }
}

// ---------------- thin GEMM for N <= 32: 128x32 tile, 4x4 per thread ---------
template <int ACT>
__global__ __launch_bounds__(256)
void gemm_bias_act_thin(const float* __restrict__ A, const float* __restrict__ W,
                        const float* __restrict__ bias, float* __restrict__ C,
                        int N, int K)
{
    __shared__ float As[8][128];
    __shared__ float Bs[8][33];

    const int tid = threadIdx.x;
    const int block_row = blockIdx.y * 128;

    const int tx = tid & 7;        // 0..7  -> cols tx*4..+3
    const int ty = tid >> 3;       // 0..31 -> rows ty*4..+3

    const int a_r = tid >> 1;
    const int a_c = (tid & 1) * 4;
    const int b_k = tid >> 5;      // 0..7
    const int b_c = tid & 31;      // 0..31

    const float* Arow = A + (size_t)(block_row + a_r) * K;

    float acc[4][4];
#pragma unroll
    for (int i = 0; i < 4; i++)
#pragma unroll
        for (int j = 0; j < 4; j++) acc[i][j] = 0.f;

    for (int k0 = 0; k0 < K; k0 += 8) {
#pragma unroll
        for (int u = 0; u < 4; u++) {
            int k = k0 + a_c + u;
            As[a_c + u][a_r] = (k < K) ? Arow[k] : 0.f;
        }
        {
            int k = k0 + b_k;
            Bs[b_k][b_c] = (k < K && b_c < N) ? W[(size_t)k * N + b_c] : 0.f;
        }
        __syncthreads();

#pragma unroll
        for (int kk = 0; kk < 8; kk++) {
            float ar[4], br[4];
#pragma unroll
            for (int i = 0; i < 4; i++) ar[i] = As[kk][ty * 4 + i];
#pragma unroll
            for (int j = 0; j < 4; j++) br[j] = Bs[kk][tx * 4 + j];
#pragma unroll
            for (int i = 0; i < 4; i++)
#pragma unroll
                for (int j = 0; j < 4; j++)
                    acc[i][j] += ar[i] * br[j];
        }
        __syncthreads();
    }

#pragma unroll
    for (int i = 0; i < 4; i++) {
        int row = block_row + ty * 4 + i;
#pragma unroll
        for (int j = 0; j < 4; j++) {
            int col = tx * 4 + j;
            if (col < N) {
                float v = acc[i][j] + bias[col];
                if (ACT) v = fast_tanh(v);
                C[(size_t)row * N + col] = v;
            }
        }
    }
}

// ---------------- LTC scan: one CTA per batch element ------------------------
// 256 threads: thread = j*4 + q; column j in [0,64), q in [0,4) owns 16
// presynaptic rows i = q*16+m. sigmoid(x) = 0.5 + 0.5*tanh(0.5*x); constant
// halves folded into init-time reduced per-column constants. Reduction is a
// 2-level shuffle over the 4-lane group (vs 3 levels before).
__global__ __launch_bounds__(256)
void ltc_scan(const float* __restrict__ h20, float* __restrict__ o4,
              const float* __restrict__ gleak, const float* __restrict__ vleak,
              const float* __restrict__ cm,    const float* __restrict__ w,
              const float* __restrict__ mu,    const float* __restrict__ sigma,
              const float* __restrict__ erev,  const float* __restrict__ sw,
              const float* __restrict__ smu,   const float* __restrict__ ssigma,
              const float* __restrict__ serev, const float* __restrict__ in_w,
              const float* __restrict__ in_b,  const float* __restrict__ out_w,
              const float* __restrict__ out_b)
{
    __shared__ float sh_h[TT * 20];
    __shared__ float sv[2][UNITS];

    const int b   = blockIdx.x;
    const int tid = threadIdx.x;
    const int j   = tid >> 2;      // column 0..63
    const int q   = tid & 3;       // row-group 0..3

    // ---- recurrent synapse constants (16 per thread), tanh-folded ----
    // 0.5*(v - mu)*sigma = v*ha[m] - hb[m]
    float ha[16], hb[16], we2[16], wr2[16];
    float cnum = 0.f, cden = 0.f;
#pragma unroll
    for (int m = 0; m < 16; m++) {
        int i   = q * 16 + m;
        int idx = i * UNITS + j;
        float s_ = sigma[idx];
        ha[m] = 0.5f * s_;
        hb[m] = 0.5f * mu[idx] * s_;
        float wv = 0.5f * w[idx];
        wr2[m] = wv;
        we2[m] = wv * erev[idx];
        cnum += we2[m];
        cden += wr2[m];
    }

    // ---- sensory synapse constants: k = q + 4m, m = 0..4 (5 per lane) ----
    float sA[5], sB[5], swe2[5], swr2[5];
#pragma unroll
    for (int m = 0; m < 5; m++) {
        int k   = q + 4 * m;
        int idx = k * UNITS + j;
        float s_ = ssigma[idx];
        sA[m] = 0.5f * in_w[k] * s_;
        sB[m] = 0.5f * (in_b[k] - smu[idx]) * s_;
        float wv = 0.5f * sw[idx];
        swr2[m] = wv;
        swe2[m] = wv * serev[idx];
        cnum += swe2[m];
        cden += swr2[m];
    }

    // reduce constant halves over the 4-lane group
#pragma unroll
    for (int off = 1; off < 4; off <<= 1) {
        cnum += __shfl_xor_sync(0xffffffffu, cnum, off);
        cden += __shfl_xor_sync(0xffffffffu, cden, off);
    }

    const float cmt    = cm[j] * (float)UNFOLDS;        // cm / (1/6)
    const float addnum = gleak[j] * vleak[j] + cnum;
    const float denbas = cmt + gleak[j] + cden + 1e-8f;
    float ow = 0.f, ob = 0.f;
    if (j < MOTOR) { ow = out_w[j]; ob = out_b[j]; }

    // ---- stage full h sequence for this batch into SMEM ----
    for (int idx = tid; idx < TT * 20; idx += 256)
        sh_h[idx] = h20[(size_t)b * (TT * 20) + idx];
    if (tid < UNITS) sv[0][tid] = 0.f;
    __syncthreads();

    int   p  = 0;
    float vj = 0.f;

    for (int t = 0; t < TT; t++) {
        // ---- sensory tanh-part (once per step), 5 per lane ----
        float wns = 0.f, wds = 0.f;
#pragma unroll
        for (int m = 0; m < 5; m++) {
            float uk = sh_h[t * 20 + (q + 4 * m)];
            float tt = fast_tanh(fmaf(uk, sA[m], sB[m]));
            wns = fmaf(swe2[m], tt, wns);
            wds = fmaf(swr2[m], tt, wds);
        }
#pragma unroll
        for (int off = 1; off < 4; off <<= 1) {
            wns += __shfl_xor_sync(0xffffffffu, wns, off);
            wds += __shfl_xor_sync(0xffffffffu, wds, off);
        }

        // ---- 6 semi-implicit ODE unfolds ----
#pragma unroll
        for (int uf = 0; uf < UNFOLDS; uf++) {
            const float4 v0 = *(const float4*)&sv[p][q * 16 + 0];
            const float4 v1 = *(const float4*)&sv[p][q * 16 + 4];
            const float4 v2 = *(const float4*)&sv[p][q * 16 + 8];
            const float4 v3 = *(const float4*)&sv[p][q * 16 + 12];
            float vr[16] = {v0.x, v0.y, v0.z, v0.w, v1.x, v1.y, v1.z, v1.w,
                            v2.x, v2.y, v2.z, v2.w, v3.x, v3.y, v3.z, v3.w};

            // two independent accumulator pairs to shorten the FMA chains
            float an0 = 0.f, ad0 = 0.f, an1 = 0.f, ad1 = 0.f;
#pragma unroll
            for (int m = 0; m < 8; m++) {
                float t0 = fast_tanh(fmaf(vr[m],     ha[m],     -hb[m]));
                float t1 = fast_tanh(fmaf(vr[m + 8], ha[m + 8], -hb[m + 8]));
                an0 = fmaf(we2[m],     t0, an0);
                ad0 = fmaf(wr2[m],     t0, ad0);
                an1 = fmaf(we2[m + 8], t1, an1);
                ad1 = fmaf(wr2[m + 8], t1, ad1);
            }
            float an = an0 + an1, ad = ad0 + ad1;
#pragma unroll
            for (int off = 1; off < 4; off <<= 1) {
                an += __shfl_xor_sync(0xffffffffu, an, off);
                ad += __shfl_xor_sync(0xffffffffu, ad, off);
            }
            float num = fmaf(cmt, vj, addnum) + an + wns;
            float den = denbas + ad + wds;
            vj = num * fast_rcp(den);
            if (q == 0) sv[p ^ 1][j] = vj;
            __syncthreads();
            p ^= 1;
        }

        // ---- motor readout ----
        if (j < MOTOR && q == 0)
            o4[((size_t)b * TT + t) * MOTOR + j] = fmaf(vj, ow, ob);
    }
}

// ---------------- launcher ---------------------------------------------------
extern "C" void kernel_launch(void* const* d_in, const int* in_sizes, int n_in,
                              void* d_out, int out_size)
{
    const float* x     = (const float*)d_in[0];
    const float* ew0   = (const float*)d_in[1];
    const float* eb0   = (const float*)d_in[2];
    const float* ew1   = (const float*)d_in[3];
    const float* eb1   = (const float*)d_in[4];
    const float* ew2   = (const float*)d_in[5];
    const float* eb2   = (const float*)d_in[6];
    const float* dw0   = (const float*)d_in[7];
    const float* db0   = (const float*)d_in[8];
    const float* dw1   = (const float*)d_in[9];
    const float* db1   = (const float*)d_in[10];
    const float* dw2   = (const float*)d_in[11];
    const float* db2   = (const float*)d_in[12];
    const float* gleak = (const float*)d_in[13];
    const float* vleak = (const float*)d_in[14];
    const float* cm    = (const float*)d_in[15];
    const float* w     = (const float*)d_in[16];
    const float* mu    = (const float*)d_in[17];
    const float* sigma = (const float*)d_in[18];
    const float* erev  = (const float*)d_in[19];
    const float* sw    = (const float*)d_in[20];
    const float* smu   = (const float*)d_in[21];
    const float* ssig  = (const float*)d_in[22];
    const float* serev = (const float*)d_in[23];
    const float* in_w  = (const float*)d_in[24];
    const float* in_b  = (const float*)d_in[25];
    const float* out_w = (const float*)d_in[26];
    const float* out_b = (const float*)d_in[27];
    float* out = (float*)d_out;

    float *buf0, *buf1, *h20, *o4;
    cudaGetSymbolAddress((void**)&buf0, g_buf0);
    cudaGetSymbolAddress((void**)&buf1, g_buf1);
    cudaGetSymbolAddress((void**)&h20,  g_h20);
    cudaGetSymbolAddress((void**)&o4,   g_o4);

    dim3 blk(256);
    dim3 grid500(4, MROWS / 128);   // N=500 -> 4 col blocks
    dim3 gridthin(1, MROWS / 128);  // N<=32 -> thin kernel

    // encoder: 39 -> 500 -> 500 -> 20
    gemm_bias_act<1><<<grid500, blk>>>(x,    ew0, eb0, buf0, 500, 39);
    gemm_bias_act<1><<<grid500, blk>>>(buf0, ew1, eb1, buf1, 500, 500);
    gemm_bias_act_thin<0><<<gridthin, blk>>>(buf1, ew2, eb2, h20, 20, 500);

    // LTC scan over T
    ltc_scan<<<BB, 256>>>(h20, o4, gleak, vleak, cm, w, mu, sigma, erev,
                          sw, smu, ssig, serev, in_w, in_b, out_w, out_b);

    // decoder: 4 -> 500 -> 500 -> 30
    gemm_bias_act<1><<<grid500, blk>>>(o4,   dw0, db0, buf0, 500, 4);
    gemm_bias_act<1><<<grid500, blk>>>(buf0, dw1, db1, buf1, 500, 500);
    gemm_bias_act_thin<0><<<gridthin, blk>>>(buf1, dw2, db2, out, 30, 500);
}